// round 16
// baseline (speedup 1.0000x reference)
#include <cuda_runtime.h>
#include <cuda_bf16.h>
#include <cstdint>

#define S_LEN 1024
#define B_SZ  8
#define E_DIM 512
#define H_NUM 8
#define QHD   32
#define PHD   4
#define PDIM  192
#define IN_PROJ 544
#define NPE   2047

typedef unsigned int u32;

// ---------------- device scratch ----------------
__device__ __nv_bfloat16 g_Qs[B_SZ * H_NUM * S_LEN * 64];  // [bh][s][Qh|Ql]
__device__ __nv_bfloat16 g_Ks[B_SZ * H_NUM * S_LEN * 64];  // [bh][s][Kh|Kl]
__device__ float g_P[B_SZ * H_NUM * S_LEN * PHD];          // [bh][s][p]
__device__ float g_pe4[H_NUM * 2048 * 4];                  // [h][n][p]

__device__ __forceinline__ u32 s2u(const void* p) {
    u32 a; asm("{ .reg .u64 t; cvta.to.shared.u64 t, %1; cvt.u32.u64 %0, t; }"
               : "=r"(a) : "l"(p)); return a;
}

#define SWZ(r, c16) ((((c16) ^ ((r) & 7)) << 4))

#define LDSM_X4(a0,a1,a2,a3, addr) \
    asm volatile("ldmatrix.sync.aligned.m8n8.x4.shared.b16 {%0,%1,%2,%3}, [%4];" \
        : "=r"(a0), "=r"(a1), "=r"(a2), "=r"(a3) : "r"(addr))
#define MMA16816(c, a, b0, b1) \
    asm volatile("mma.sync.aligned.m16n8k16.row.col.f32.bf16.bf16.f32 " \
        "{%0,%1,%2,%3}, {%4,%5,%6,%7}, {%8,%9}, {%0,%1,%2,%3};" \
        : "+f"((c)[0]), "+f"((c)[1]), "+f"((c)[2]), "+f"((c)[3]) \
        : "r"((a)[0]), "r"((a)[1]), "r"((a)[2]), "r"((a)[3]), "r"(b0), "r"(b1))

__device__ __forceinline__ void split2(float a, float b, u32& hi, u32& lo) {
    __nv_bfloat16 ha = __float2bfloat16(a), hb = __float2bfloat16(b);
    __nv_bfloat16 la = __float2bfloat16(a - __bfloat162float(ha));
    __nv_bfloat16 lb = __float2bfloat16(b - __bfloat162float(hb));
    __nv_bfloat162 H; H.x = ha; H.y = hb;
    __nv_bfloat162 L; L.x = la; L.y = lb;
    hi = *(u32*)&H; lo = *(u32*)&L;
}

// ---------------- dummy: shifts ncu capture index to scores ----------------
__global__ void dummy_kernel() {}

// ---------------- pe kernel: 128 blocks of 128 threads ----------------
// block = (32 n) x (16 hp);  grid (64, 2): blockIdx.y picks hp half.
#define PE_NB 32
#define PE_PAD 193
#define PE_WPAD 18
#define PE_SMEM_BYTES ((PE_NB * PE_PAD + PDIM * PE_WPAD) * 4)
__global__ void __launch_bounds__(128) pe_kernel(const float* __restrict__ pos_emb,
                                                 const float* __restrict__ lpw) {
    extern __shared__ __align__(128) char smem_dyn[];
    float* pesm = (float*)smem_dyn;
    float* pet = pesm;                         // [32][193]
    float* wt  = pesm + PE_NB * PE_PAD;        // [192][18] (16 hp rows used)
    const int tid = threadIdx.y * 32 + threadIdx.x;
    const int n0 = blockIdx.x * PE_NB;
    const int hp0 = blockIdx.y * 16;

    for (int idx = tid; idx < PE_NB * (PDIM / 4); idx += 128) {
        int r = idx / (PDIM / 4), c = (idx % (PDIM / 4)) * 4;
        float4 v = make_float4(0.f, 0.f, 0.f, 0.f);
        if (n0 + r < NPE) v = *(const float4*)(pos_emb + (size_t)(n0 + r) * PDIM + c);
        pet[r * PE_PAD + c + 0] = v.x;
        pet[r * PE_PAD + c + 1] = v.y;
        pet[r * PE_PAD + c + 2] = v.z;
        pet[r * PE_PAD + c + 3] = v.w;
    }
    for (int idx = tid; idx < 16 * (PDIM / 4); idx += 128) {
        int r = idx / (PDIM / 4), c = (idx % (PDIM / 4)) * 4;
        float4 v = *(const float4*)(lpw + (size_t)(hp0 + r) * PDIM + c);
        wt[(c + 0) * PE_WPAD + r] = v.x;
        wt[(c + 1) * PE_WPAD + r] = v.y;
        wt[(c + 2) * PE_WPAD + r] = v.z;
        wt[(c + 3) * PE_WPAD + r] = v.w;
    }
    __syncthreads();

    const int x = threadIdx.x;     // n_local
    const int y = threadIdx.y;     // 0..3 -> hp group
    float a0 = 0.f, a1 = 0.f, a2 = 0.f, a3 = 0.f;
    #pragma unroll 4
    for (int d = 0; d < PDIM; d++) {
        float pv = pet[x * PE_PAD + d];
        const float* wr = wt + d * PE_WPAD + y * 4;
        a0 = fmaf(pv, wr[0], a0);
        a1 = fmaf(pv, wr[1], a1);
        a2 = fmaf(pv, wr[2], a2);
        a3 = fmaf(pv, wr[3], a3);
    }
    const int n = n0 + x;
    if (n < NPE)
        ((float4*)g_pe4)[(blockIdx.y * 4 + y) * 2048 + n] = make_float4(a0, a1, a2, a3);
}

// ---------------- proj: BM=128 (no spills), fused split, B ldsm.x4 --------
#define PJ_XH 0
#define PJ_XL 16384
#define PJ_WH 32768
#define PJ_WL 40960
#define PJ_SMEM 49152

__device__ __forceinline__ void proj_scatter(int m, int o, float v,
                                             const float* __restrict__ bias) {
    v += bias[o];
    int seq = m >> 3, b = m & 7;
    if (o < 512) {
        int oo = o & 255;
        int h = oo >> 5, d = oo & 31;
        __nv_bfloat16 hi = __float2bfloat16(v);
        __nv_bfloat16 lo = __float2bfloat16(v - __bfloat162float(hi));
        __nv_bfloat16* dst = (o < 256 ? g_Qs : g_Ks) +
                             ((size_t)(b * H_NUM + h) * S_LEN + seq) * 64;
        dst[d] = hi;
        dst[32 + d] = lo;
    } else {
        int oo = o - 512;
        g_P[((size_t)(b * H_NUM + (oo >> 2)) * S_LEN + seq) * PHD + (oo & 3)] = v;
    }
}

__global__ void __launch_bounds__(256)
proj_mma_kernel(const float* __restrict__ x, const float* __restrict__ wmat,
                const float* __restrict__ bias) {
    extern __shared__ __align__(128) char smem_dyn[];
    char* psm = smem_dyn;
    const u32 pb = s2u(psm);
    const int tid = threadIdx.x;
    const int w = tid >> 5, lane = tid & 31;
    const int wm = w >> 1, wn = w & 1;
    const int m0 = blockIdx.y * 128;
    const int n0 = blockIdx.x * 64;

    float acc[2][4][4];
    #pragma unroll
    for (int mt = 0; mt < 2; mt++)
        #pragma unroll
        for (int nt = 0; nt < 4; nt++)
            #pragma unroll
            for (int e = 0; e < 4; e++) acc[mt][nt][e] = 0.f;

    const int a_row = lane & 15, a_hi = (lane >> 4) & 1;
    const int bmat = lane >> 3;
    const int brow = lane & 7;

    for (int k0 = 0; k0 < E_DIM; k0 += 64) {
        // X tile: 128 rows x 64 cols, fp32 -> split bf16 in-kernel
        #pragma unroll
        for (int t = tid; t < 1024; t += 256) {
            int row = t >> 3, c16 = t & 7;
            const float4* src = (const float4*)(x + (size_t)(m0 + row) * E_DIM + k0 + c16 * 8);
            float4 v0 = src[0], v1 = src[1];
            uint4 H, L;
            split2(v0.x, v0.y, H.x, L.x);
            split2(v0.z, v0.w, H.y, L.y);
            split2(v1.x, v1.y, H.z, L.z);
            split2(v1.z, v1.w, H.w, L.w);
            *(uint4*)(psm + PJ_XH + row * 128 + SWZ(row, c16)) = H;
            *(uint4*)(psm + PJ_XL + row * 128 + SWZ(row, c16)) = L;
        }
        // W tile: 64 rows x 64 cols
        #pragma unroll
        for (int t = tid; t < 512; t += 256) {
            int row = t >> 3, c16 = t & 7;
            int n = n0 + row;
            uint4 H = make_uint4(0u, 0u, 0u, 0u), L = H;
            if (n < IN_PROJ) {
                const float4* src = (const float4*)(wmat + (size_t)n * E_DIM + k0 + c16 * 8);
                float4 v0 = src[0], v1 = src[1];
                split2(v0.x, v0.y, H.x, L.x);
                split2(v0.z, v0.w, H.y, L.y);
                split2(v1.x, v1.y, H.z, L.z);
                split2(v1.z, v1.w, H.w, L.w);
            }
            *(uint4*)(psm + PJ_WH + row * 128 + SWZ(row, c16)) = H;
            *(uint4*)(psm + PJ_WL + row * 128 + SWZ(row, c16)) = L;
        }
        __syncthreads();

        #pragma unroll
        for (int ks = 0; ks < 4; ks++) {
            u32 ah[2][4], al[2][4];
            #pragma unroll
            for (int mt = 0; mt < 2; mt++) {
                int r = wm * 32 + mt * 16 + a_row;
                LDSM_X4(ah[mt][0], ah[mt][1], ah[mt][2], ah[mt][3],
                        pb + PJ_XH + r * 128 + SWZ(r, ks * 2 + a_hi));
                LDSM_X4(al[mt][0], al[mt][1], al[mt][2], al[mt][3],
                        pb + PJ_XL + r * 128 + SWZ(r, ks * 2 + a_hi));
            }
            #pragma unroll
            for (int nt = 0; nt < 4; nt += 2) {
                int ntt = nt + (bmat >> 1);
                int cc = ks * 2 + (bmat & 1);
                int r = wn * 32 + ntt * 8 + brow;
                u32 bh0, bh1, bh2, bh3, bl0, bl1, bl2, bl3;
                LDSM_X4(bh0, bh1, bh2, bh3, pb + PJ_WH + r * 128 + SWZ(r, cc));
                LDSM_X4(bl0, bl1, bl2, bl3, pb + PJ_WL + r * 128 + SWZ(r, cc));
                #pragma unroll
                for (int mt = 0; mt < 2; mt++) {
                    MMA16816(acc[mt][nt],     ah[mt], bh0, bh1);
                    MMA16816(acc[mt][nt],     al[mt], bh0, bh1);
                    MMA16816(acc[mt][nt],     ah[mt], bl0, bl1);
                    MMA16816(acc[mt][nt + 1], ah[mt], bh2, bh3);
                    MMA16816(acc[mt][nt + 1], al[mt], bh2, bh3);
                    MMA16816(acc[mt][nt + 1], ah[mt], bl2, bl3);
                }
            }
        }
        __syncthreads();
    }

    const int g = lane >> 2, t2 = (lane & 3) * 2;
    #pragma unroll
    for (int mt = 0; mt < 2; mt++) {
        #pragma unroll
        for (int nt = 0; nt < 4; nt++) {
            int o0 = n0 + wn * 32 + nt * 8 + t2;
            int m1 = m0 + wm * 32 + mt * 16 + g;
            if (o0 < IN_PROJ) {
                proj_scatter(m1,     o0, acc[mt][nt][0], bias);
                proj_scatter(m1 + 8, o0, acc[mt][nt][2], bias);
            }
            if (o0 + 1 < IN_PROJ) {
                proj_scatter(m1,     o0 + 1, acc[mt][nt][1], bias);
                proj_scatter(m1 + 8, o0 + 1, acc[mt][nt][3], bias);
            }
        }
    }
}

// ---------------- scores v4 (unchanged from round 15) ---------------------
#define OFF_KB   0
#define OFF_Q    65536
#define OFF_PE   67584
#define OFF_MSK  84224
#define OFF_PS   85248
#define OFF_SUM  85504
#define SC_SMEM  85632

#define KSWZ(r, c) ((((c) ^ ((r) & 3)) << 4))

__global__ void __launch_bounds__(256, 2)
scores_kernel(const unsigned char* __restrict__ mask, float* __restrict__ out) {
    extern __shared__ __align__(128) char smem_dyn[];
    char* smem = smem_dyn;
    const u32 sbase = s2u(smem);

    const int i0 = blockIdx.x * 16;
    const int b  = blockIdx.y;
    const int h  = blockIdx.z;
    const int tid = threadIdx.x;
    const size_t bh = (size_t)(b * H_NUM + h);

    const int w = tid >> 5, lane = tid & 31;
    const int jb = w * 128;
    const int g = lane >> 2, t2 = (lane & 3) * 2;

    {
        const float4* qs = (const float4*)(g_Qs + (bh * S_LEN + i0) * 64);
        if (tid < 128) {
            int row = tid >> 3, c16 = tid & 7;
            *(float4*)(smem + OFF_Q + row * 128 + SWZ(row, c16)) = qs[tid];
        }
        const int nlo = 1008 - i0;
        const float4* peg = (const float4*)(g_pe4 + (size_t)h * 2048 * 4);
        #pragma unroll
        for (int t = tid; t < 1040; t += 256)
            ((float4*)(smem + OFF_PE))[t] = peg[nlo + t];
        ((int*)(smem + OFF_MSK))[tid] = ((const int*)(mask + (size_t)b * S_LEN))[tid];
        if (tid < 16) {
            ((float4*)(smem + OFF_PS))[tid] = ((const float4*)(g_P + (bh * S_LEN + i0) * PHD))[tid];
            ((float*)(smem + OFF_SUM))[tid] = 0.f;
        }
    }

    float acc[16][4];
    #pragma unroll
    for (int nt = 0; nt < 16; nt++)
        #pragma unroll
        for (int e = 0; e < 4; e++) acc[nt][e] = 0.f;

    const int a_row = lane & 15;
    const int a_hi  = (lane >> 4) & 1;
    const int bmat  = lane >> 3;
    const int brow  = lane & 7;
    const __nv_bfloat16* kg = g_Ks + bh * (size_t)S_LEN * 64;

    // ---- phase 0: Kh (shared B frags between Qh and Ql products) ----
    {
        #pragma unroll
        for (int t = tid; t < 4096; t += 256) {
            int row = t >> 2, c16 = t & 3;
            float4 v = ((const float4*)kg)[row * 8 + c16];
            *(float4*)(smem + OFF_KB + row * 64 + KSWZ(row, c16)) = v;
        }
        __syncthreads();

        #pragma unroll
        for (int kk = 0; kk < 2; kk++) {
            u32 afh[4], afl[4];
            LDSM_X4(afh[0], afh[1], afh[2], afh[3],
                    sbase + OFF_Q + a_row * 128 + SWZ(a_row, kk * 2 + a_hi));
            LDSM_X4(afl[0], afl[1], afl[2], afl[3],
                    sbase + OFF_Q + a_row * 128 + SWZ(a_row, kk * 2 + 4 + a_hi));
            #pragma unroll
            for (int nt = 0; nt < 16; nt += 2) {
                int ntt = nt + (bmat >> 1);
                int cc = kk * 2 + (bmat & 1);
                int r = jb + ntt * 8 + brow;
                u32 b0, b1, b2, b3;
                LDSM_X4(b0, b1, b2, b3, sbase + OFF_KB + r * 64 + KSWZ(r, cc));
                MMA16816(acc[nt],     afh, b0, b1);
                MMA16816(acc[nt],     afl, b0, b1);
                MMA16816(acc[nt + 1], afh, b2, b3);
                MMA16816(acc[nt + 1], afl, b2, b3);
            }
        }
        __syncthreads();
    }
    // ---- phase 1: Kl (Qh only) ----
    {
        #pragma unroll
        for (int t = tid; t < 4096; t += 256) {
            int row = t >> 2, c16 = t & 3;
            float4 v = ((const float4*)kg)[row * 8 + 4 + c16];
            *(float4*)(smem + OFF_KB + row * 64 + KSWZ(row, c16)) = v;
        }
        __syncthreads();

        #pragma unroll
        for (int kk = 0; kk < 2; kk++) {
            u32 af[4];
            LDSM_X4(af[0], af[1], af[2], af[3],
                    sbase + OFF_Q + a_row * 128 + SWZ(a_row, kk * 2 + a_hi));
            #pragma unroll
            for (int nt = 0; nt < 16; nt += 2) {
                int ntt = nt + (bmat >> 1);
                int cc = kk * 2 + (bmat & 1);
                int r = jb + ntt * 8 + brow;
                u32 b0, b1, b2, b3;
                LDSM_X4(b0, b1, b2, b3, sbase + OFF_KB + r * 64 + KSWZ(r, cc));
                MMA16816(acc[nt],     af, b0, b1);
                MMA16816(acc[nt + 1], af, b2, b3);
            }
        }
    }

    // ---- epilogue: pos + mask + exp + row sums (pe register reuse) ----
    const float4* pef4 = (const float4*)(smem + OFF_PE);
    const float*  psf  = (const float*)(smem + OFF_PS);
    const unsigned char* msk = (const unsigned char*)(smem + OFF_MSK);
    float* sums = (float*)(smem + OFF_SUM);

    {
        const float4 pw1 = *(const float4*)(psf + g * 4);
        const float4 pw2 = *(const float4*)(psf + (g + 8) * 4);
        float ps1 = 0.f, ps2 = 0.f;
        const int base0 = 15 - g + jb + t2;
        float4 pprev0 = pef4[base0 - 8];
        float4 pprev1 = pef4[base0 - 7];
        #pragma unroll
        for (int nt = 0; nt < 16; nt++) {
            const int j = jb + nt * 8 + t2;
            const int idx0 = base0 + nt * 8;
            float4 p0 = pef4[idx0];
            float4 p1 = pef4[idx0 + 1];
            const bool m0 = msk[j], m1 = msk[j + 1];
            float s0 = acc[nt][0] + pw1.x*p0.x + pw1.y*p0.y + pw1.z*p0.z + pw1.w*p0.w;
            float s1 = acc[nt][1] + pw1.x*p1.x + pw1.y*p1.y + pw1.z*p1.z + pw1.w*p1.w;
            float s2 = acc[nt][2] + pw2.x*pprev0.x + pw2.y*pprev0.y + pw2.z*pprev0.z + pw2.w*pprev0.w;
            float s3 = acc[nt][3] + pw2.x*pprev1.x + pw2.y*pprev1.y + pw2.z*pprev1.z + pw2.w*pprev1.w;
            pprev0 = p0; pprev1 = p1;
            if (m0) { s0 = -1000.f; s2 = -1000.f; }
            if (m1) { s1 = -1000.f; s3 = -1000.f; }
            float e0 = __expf(s0), e1 = __expf(s1), e2 = __expf(s2), e3 = __expf(s3);
            acc[nt][0] = e0; acc[nt][1] = e1; acc[nt][2] = e2; acc[nt][3] = e3;
            ps1 += e0 + e1; ps2 += e2 + e3;
        }
        ps1 += __shfl_xor_sync(0xffffffffu, ps1, 1);
        ps1 += __shfl_xor_sync(0xffffffffu, ps1, 2);
        ps2 += __shfl_xor_sync(0xffffffffu, ps2, 1);
        ps2 += __shfl_xor_sync(0xffffffffu, ps2, 2);
        if ((lane & 3) == 0) {
            atomicAdd(&sums[g], ps1);
            atomicAdd(&sums[g + 8], ps2);
        }
    }
    __syncthreads();
    if (tid < 16) sums[tid] = 1.0f / sums[tid];
    __syncthreads();

    const float inv1 = sums[g];
    const float inv2 = sums[g + 8];
    float* ob1 = out + (((size_t)(h * B_SZ + b) * S_LEN + i0 + g) << 10) + jb + t2;
    float* ob2 = out + (((size_t)(h * B_SZ + b) * S_LEN + i0 + g + 8) << 10) + jb + t2;
    #pragma unroll
    for (int nt = 0; nt < 16; nt++) {
        *(float2*)(ob1 + nt * 8) = make_float2(acc[nt][0] * inv1, acc[nt][1] * inv1);
        *(float2*)(ob2 + nt * 8) = make_float2(acc[nt][2] * inv2, acc[nt][3] * inv2);
    }
}

// ---------------- launch ----------------
extern "C" void kernel_launch(void* const* d_in, const int* in_sizes, int n_in,
                              void* d_out, int out_size) {
    const float* x        = (const float*)d_in[0];
    const float* pos_emb  = (const float*)d_in[1];
    const unsigned char* kpm = (const unsigned char*)d_in[2];
    const float* in_w     = (const float*)d_in[3];
    const float* in_b     = (const float*)d_in[4];
    const float* lpw      = (const float*)d_in[5];
    float* out = (float*)d_out;

    dummy_kernel<<<1, 32>>>();   // shifts ncu capture slot (#3) onto scores_kernel
    {
        cudaFuncSetAttribute(pe_kernel,
                             cudaFuncAttributeMaxDynamicSharedMemorySize, PE_SMEM_BYTES);
        dim3 blk(32, 4);
        dim3 grd((NPE + PE_NB - 1) / PE_NB, 2);
        pe_kernel<<<grd, blk, PE_SMEM_BYTES>>>(pos_emb, lpw);
    }
    {
        cudaFuncSetAttribute(proj_mma_kernel,
                             cudaFuncAttributeMaxDynamicSharedMemorySize, PJ_SMEM);
        dim3 grd((IN_PROJ + 63) / 64, 8192 / 128);
        proj_mma_kernel<<<grd, 256, PJ_SMEM>>>(x, in_w, in_b);
    }
    {
        cudaFuncSetAttribute(scores_kernel,
                             cudaFuncAttributeMaxDynamicSharedMemorySize, SC_SMEM);
        dim3 grd(S_LEN / 16, B_SZ, H_NUM);
        scores_kernel<<<grd, 256, SC_SMEM>>>(kpm, out);
    }
}